// round 16
// baseline (speedup 1.0000x reference)
#include <cuda_runtime.h>
#include <cuda_bf16.h>
#include <float.h>

#define D 128
#define KN 32
#define MAXN 50000
#define CSTR 40       // node: bf16 elems per chunk row (32 + 8 pad) -> 80 B
#define PSTR 136      // proj: bf16 elems per smem row (128 + 8 pad)
#define FULLM 0xffffffffu

// packed projected features: per element u32 = (lo_bf16 << 16) | hi_bf16
__device__ unsigned g_p[(size_t)MAXN * D];
// transposed weight hi/lo (wt[n][k]), bf16
__device__ __nv_bfloat16 g_wt_hi[D * D];
__device__ __nv_bfloat16 g_wt_lo[D * D];

// ---- mma / ldmatrix helpers ----
__device__ __forceinline__ void ldm_x4(unsigned (&r)[4], unsigned addr) {
    asm volatile("ldmatrix.sync.aligned.m8n8.x4.shared.b16 {%0,%1,%2,%3}, [%4];"
                 : "=r"(r[0]), "=r"(r[1]), "=r"(r[2]), "=r"(r[3]) : "r"(addr));
}
__device__ __forceinline__ void mma4(float* d, const unsigned* a,
                                     unsigned b0, unsigned b1) {
    asm volatile(
        "mma.sync.aligned.m16n8k16.row.col.f32.bf16.bf16.f32 "
        "{%0,%1,%2,%3},{%4,%5,%6,%7},{%8,%9},{%0,%1,%2,%3};"
        : "+f"(d[0]), "+f"(d[1]), "+f"(d[2]), "+f"(d[3])
        : "r"(a[0]), "r"(a[1]), "r"(a[2]), "r"(a[3]), "r"(b0), "r"(b1));
}
__device__ __forceinline__ float sqrt_approx(float x) {
    float r;
    asm("sqrt.approx.f32 %0, %1;" : "=f"(r) : "f"(x));
    return r;
}
// unpack helpers: element fp32 value = hi + lo
__device__ __forceinline__ float unpack_val(unsigned p) {
    return __uint_as_float(p << 16) + __uint_as_float(p & 0xffff0000u);
}
__device__ __forceinline__ unsigned bf2u(__nv_bfloat16 a, __nv_bfloat16 b) {
    __nv_bfloat162 p = __halves2bfloat162(a, b);
    return *reinterpret_cast<unsigned*>(&p);
}
__device__ __forceinline__ unsigned packhl(float v) {
    __nv_bfloat16 h = __float2bfloat16_rn(v);
    __nv_bfloat16 l = __float2bfloat16_rn(v - __bfloat162float(h));
    unsigned hb = *reinterpret_cast<unsigned short*>(&h);
    unsigned lb = *reinterpret_cast<unsigned short*>(&l);
    return (lb << 16) | hb;
}
__device__ __forceinline__ float warp_max32(float v) {
#pragma unroll
    for (int off = 16; off > 0; off >>= 1)
        v = fmaxf(v, __shfl_xor_sync(FULLM, v, off));
    return v;
}
__device__ __forceinline__ float warp_sum32(float v) {
#pragma unroll
    for (int off = 16; off > 0; off >>= 1)
        v += __shfl_xor_sync(FULLM, v, off);
    return v;
}

// ---------------------------------------------------------------------------
// wconv: weight[k][n] fp32 -> transposed bf16 hi/lo wt[n][k]
// ---------------------------------------------------------------------------
__global__ __launch_bounds__(128) void wconv(const float* __restrict__ weight) {
    int idx = blockIdx.x * 128 + threadIdx.x;   // grid 128 x 128
    int k = idx >> 7, nn = idx & 127;
    float v = weight[idx];
    __nv_bfloat16 h = __float2bfloat16_rn(v);
    __nv_bfloat16 l = __float2bfloat16_rn(v - __bfloat162float(h));
    g_wt_hi[nn * D + k] = h;
    g_wt_lo[nn * D + k] = l;
}

// ---------------------------------------------------------------------------
// proj_mma: h = feat @ weight via bf16 hi/lo mma.sync, packed epilogue.
// ---------------------------------------------------------------------------
#define SM_FA_HI 0
#define SM_FA_LO (64 * PSTR)
#define SM_WB_HI (2 * 64 * PSTR)
#define SM_WB_LO (2 * 64 * PSTR + 128 * PSTR)
#define SMEM_PROJ ((2 * 64 * PSTR + 2 * 128 * PSTR) * 2)

__global__ __launch_bounds__(128) void proj_mma(const float* __restrict__ feat,
                                                int n) {
    extern __shared__ __align__(16) unsigned short sm[];
    unsigned short* fa_hi = sm + SM_FA_HI;
    unsigned short* fa_lo = sm + SM_FA_LO;
    unsigned short* wb_hi = sm + SM_WB_HI;
    unsigned short* wb_lo = sm + SM_WB_LO;

    const int tid  = threadIdx.x;
    const int lane = tid & 31;
    const int warp = tid >> 5;
    const int row0 = blockIdx.x * 64;

    // ---- stage feat tile (64 x 128 fp32 -> hi/lo bf16) ----
#pragma unroll
    for (int i = 0; i < 16; ++i) {
        int lin = i * 128 + tid;
        int r = lin >> 5, c = lin & 31;       // c = float4 index
        int row = row0 + r;
        float4 v = make_float4(0.f, 0.f, 0.f, 0.f);
        if (row < n) v = reinterpret_cast<const float4*>(feat)[(size_t)row * 32 + c];
        __nv_bfloat16 hx = __float2bfloat16_rn(v.x);
        __nv_bfloat16 hy = __float2bfloat16_rn(v.y);
        __nv_bfloat16 hz = __float2bfloat16_rn(v.z);
        __nv_bfloat16 hw = __float2bfloat16_rn(v.w);
        __nv_bfloat16 lx = __float2bfloat16_rn(v.x - __bfloat162float(hx));
        __nv_bfloat16 ly = __float2bfloat16_rn(v.y - __bfloat162float(hy));
        __nv_bfloat16 lz = __float2bfloat16_rn(v.z - __bfloat162float(hz));
        __nv_bfloat16 lw = __float2bfloat16_rn(v.w - __bfloat162float(hw));
        *reinterpret_cast<uint2*>(&fa_hi[r * PSTR + c * 4]) =
            make_uint2(bf2u(hx, hy), bf2u(hz, hw));
        *reinterpret_cast<uint2*>(&fa_lo[r * PSTR + c * 4]) =
            make_uint2(bf2u(lx, ly), bf2u(lz, lw));
    }

    // ---- stage weight tiles (128 x 128 bf16 each) ----
#pragma unroll
    for (int i = 0; i < 16; ++i) {
        int lin = i * 128 + tid;
        int r = lin >> 4, c = lin & 15;       // c = 8-elem (16 B) chunk
        uint4 hv = reinterpret_cast<const uint4*>(g_wt_hi + r * D)[c];
        uint4 lv = reinterpret_cast<const uint4*>(g_wt_lo + r * D)[c];
        *reinterpret_cast<uint4*>(&wb_hi[r * PSTR + c * 8]) = hv;
        *reinterpret_cast<uint4*>(&wb_lo[r * PSTR + c * 8]) = lv;
    }
    __syncthreads();

    // ---- mma mainloop: warp computes rows mw..mw+15, all n=128 ----
    const int mw = warp * 16;
    float acc[16][4];
#pragma unroll
    for (int t = 0; t < 16; ++t)
#pragma unroll
        for (int i = 0; i < 4; ++i) acc[t][i] = 0.f;

    const int trow = (lane & 7) + 8 * ((lane >> 3) & 1);
    const int tcol = 8 * (lane >> 4);
    const unsigned faHiB = (unsigned)__cvta_generic_to_shared(fa_hi);
    const unsigned faLoB = (unsigned)__cvta_generic_to_shared(fa_lo);
    const unsigned wbHiB = (unsigned)__cvta_generic_to_shared(wb_hi);
    const unsigned wbLoB = (unsigned)__cvta_generic_to_shared(wb_lo);

#pragma unroll
    for (int kk = 0; kk < D; kk += 16) {
        unsigned aoff = (unsigned)(((mw + trow) * PSTR + kk + tcol) * 2);
        unsigned ahi[4], alo[4];
        ldm_x4(ahi, faHiB + aoff);
        ldm_x4(alo, faLoB + aoff);

#pragma unroll
        for (int j = 0; j < 8; ++j) {         // n-pair j covers n = 16j..16j+15
            unsigned boff = (unsigned)(((16 * j + trow) * PSTR + kk + tcol) * 2);
            unsigned bh[4], bl[4];
            ldm_x4(bh, wbHiB + boff);
            ldm_x4(bl, wbLoB + boff);
            mma4(acc[2 * j],     ahi, bh[0], bh[2]);
            mma4(acc[2 * j],     ahi, bl[0], bl[2]);
            mma4(acc[2 * j],     alo, bh[0], bh[2]);
            mma4(acc[2 * j + 1], ahi, bh[1], bh[3]);
            mma4(acc[2 * j + 1], ahi, bl[1], bl[3]);
            mma4(acc[2 * j + 1], alo, bh[1], bh[3]);
        }
    }

    // ---- epilogue: pack to g_p ----
    const int er = lane >> 2;
    const int ec = (lane & 3) * 2;
#pragma unroll
    for (int h = 0; h < 2; ++h) {
        int row = row0 + mw + er + 8 * h;
        if (row < n) {
#pragma unroll
            for (int t = 0; t < 16; ++t) {
                unsigned p0 = packhl(acc[t][2 * h]);
                unsigned p1 = packhl(acc[t][2 * h + 1]);
                *reinterpret_cast<uint2*>(g_p + (size_t)row * D + 8 * t + ec) =
                    make_uint2(p0, p1);
            }
        }
    }
}

// ---------------------------------------------------------------------------
// Kernel B: one WARP per node. Symmetric Gram: 6 of 8 fragment tiles
// (accA = rows 0-15 x all cols; accB = rows 16-31 x cols 16-31); lower-left
// recovered via transposed reads of the stashed top-right block (stride 18
// floats keeps float2 stores 8 B-aligned).
// ---------------------------------------------------------------------------
__global__ __launch_bounds__(64, 18) void node_kernel(const void* __restrict__ top_k_idx,
                                                      const float* __restrict__ top_k_w,
                                                      const float* __restrict__ bias,
                                                      float* __restrict__ out,
                                                      int n) {
    __shared__ __align__(16) unsigned short Ahi[2][KN][CSTR];
    __shared__ __align__(16) unsigned short Alo[2][KN][CSTR];
    __shared__ float s_sq[2][KN];
    __shared__ float s_dagg[2][KN];
    __shared__ __align__(16) float s_st[2][16][18];  // top-right 16x16 gram block
    __shared__ __align__(16) float    s_r[2][KN];
    __shared__ __align__(16) unsigned s_off[2][KN];

    const int warp = threadIdx.x >> 5;
    const int lane = threadIdx.x & 31;
    const int node = blockIdx.x * 2 + warp;
    if (node >= n) return;

    int bad = 0;
    if (lane < 16) {
        long long v = reinterpret_cast<const long long*>(top_k_idx)[lane];
        bad = (v < -1 || v >= (long long)n);
    }
    const bool is64 = (__ballot_sync(FULLM, bad) == 0u);

    long long id = is64
        ? reinterpret_cast<const long long*>(top_k_idx)[(size_t)node * KN + lane]
        : (long long)reinterpret_cast<const int*>(top_k_idx)[(size_t)node * KN + lane];
    const int msk = (id < 0);
    int nbr = msk ? 0 : (int)id;
    if (nbr >= n) nbr = 0;
    const float wgt = msk ? 0.f : top_k_w[(size_t)node * KN + lane];
    s_off[warp][lane] = (unsigned)nbr * D;

    unsigned short (*ahi)[CSTR] = Ahi[warp];
    unsigned short (*alo)[CSTR] = Alo[warp];

    // accA[nt]: gram rows 0-15, cols nt*8..+7.  accB[t]: rows 16-31, cols 16+t*8..+7.
    float accA[4][4], accB[2][4];
#pragma unroll
    for (int b = 0; b < 4; ++b)
#pragma unroll
        for (int i = 0; i < 4; ++i) accA[b][i] = 0.f;
#pragma unroll
    for (int b = 0; b < 2; ++b)
#pragma unroll
        for (int i = 0; i < 4; ++i) accB[b][i] = 0.f;

    const int trow = (lane & 7) + 8 * ((lane >> 3) & 1);
    const int tcol = 8 * (lane >> 4);
    const unsigned hiB = (unsigned)__cvta_generic_to_shared(&ahi[0][0]);
    const unsigned loB = (unsigned)__cvta_generic_to_shared(&alo[0][0]);

    const int gq = lane >> 3;
    const int gc = lane & 7;

#pragma unroll
    for (int chunk = 0; chunk < 4; ++chunk) {
        // ---- gather packed chunk rows; split hi/lo via PRMT ----
#pragma unroll
        for (int it = 0; it < 8; ++it) {
            int r = it * 4 + gq;
            int src = __shfl_sync(FULLM, nbr, r);
            uint4 p = *reinterpret_cast<const uint4*>(
                g_p + (size_t)src * D + chunk * 32 + gc * 4);
            unsigned h01 = __byte_perm(p.x, p.y, 0x5410);
            unsigned h23 = __byte_perm(p.z, p.w, 0x5410);
            unsigned l01 = __byte_perm(p.x, p.y, 0x7632);
            unsigned l23 = __byte_perm(p.z, p.w, 0x7632);
            *reinterpret_cast<uint2*>(&ahi[r][gc * 4]) = make_uint2(h01, h23);
            *reinterpret_cast<uint2*>(&alo[r][gc * 4]) = make_uint2(l01, l23);
        }
        __syncwarp();

        // ---- mma-accumulate this chunk (k = 0..31), 6 tiles only ----
#pragma unroll
        for (int kk = 0; kk < 32; kk += 16) {
            unsigned o0 = (unsigned)((trow * CSTR + kk + tcol) * 2);
            unsigned o1 = (unsigned)(((16 + trow) * CSTR + kk + tcol) * 2);
            unsigned h0[4], h1[4], l0[4], l1[4];
            ldm_x4(h0, hiB + o0);
            ldm_x4(h1, hiB + o1);
            ldm_x4(l0, loB + o0);
            ldm_x4(l1, loB + o1);

            // rows 0-15 (A = h0/l0), all col tiles
#pragma unroll
            for (int nt = 0; nt < 4; ++nt) {
                const unsigned* Bh = (nt < 2) ? h0 : h1;
                const unsigned* Bl = (nt < 2) ? l0 : l1;
                unsigned bh0 = (nt & 1) ? Bh[1] : Bh[0];
                unsigned bh1 = (nt & 1) ? Bh[3] : Bh[2];
                unsigned bl0 = (nt & 1) ? Bl[1] : Bl[0];
                unsigned bl1 = (nt & 1) ? Bl[3] : Bl[2];
                mma4(accA[nt], h0, bh0, bh1);
                mma4(accA[nt], h0, bl0, bl1);
                mma4(accA[nt], l0, bh0, bh1);
            }
            // rows 16-31 (A = h1/l1), col tiles 2,3 only (cols 16-31)
#pragma unroll
            for (int t = 0; t < 2; ++t) {
                unsigned bh0 = t ? h1[1] : h1[0];
                unsigned bh1 = t ? h1[3] : h1[2];
                unsigned bl0 = t ? l1[1] : l1[0];
                unsigned bl1 = t ? l1[3] : l1[2];
                mma4(accB[t], h1, bh0, bh1);
                mma4(accB[t], h1, bl0, bl1);
                mma4(accB[t], l1, bh0, bh1);
            }
        }
        __syncwarp();
    }

    const int er = lane >> 2;
    const int ec = (lane & 3) * 2;

    // ---- diagonal -> s_sq ----
#pragma unroll
    for (int nt = 0; nt < 2; ++nt)         // rows 0-15: diag lives in nt 0,1
#pragma unroll
        for (int i = 0; i < 4; ++i) {
            int rg = er + ((i >> 1) << 3);
            int cg = nt * 8 + ec + (i & 1);
            if (rg == cg) s_sq[warp][rg] = accA[nt][i];
        }
#pragma unroll
    for (int t = 0; t < 2; ++t)            // rows 16-31: diag in col tiles 2,3
#pragma unroll
        for (int i = 0; i < 4; ++i) {
            int rg = 16 + er + ((i >> 1) << 3);
            int cg = 16 + t * 8 + ec + (i & 1);
            if (rg == cg) s_sq[warp][rg] = accB[t][i];
        }

    // ---- stash top-right 16x16 block for transposed reads ----
#pragma unroll
    for (int nt = 2; nt < 4; ++nt)
#pragma unroll
        for (int h = 0; h < 2; ++h) {
            *reinterpret_cast<float2*>(&s_st[warp][er + 8 * h][(nt - 2) * 8 + ec]) =
                make_float2(accA[nt][h * 2], accA[nt][h * 2 + 1]);
        }
    __syncwarp();

    // ---- dist + dagg partials ----
    float dp[4] = {0.f, 0.f, 0.f, 0.f};  // rows: er, er+8, 16+er, 24+er
    const float sqr[4] = { s_sq[warp][er],      s_sq[warp][er + 8],
                           s_sq[warp][16 + er], s_sq[warp][24 + er] };
#pragma unroll
    for (int nt = 0; nt < 4; ++nt) {
#pragma unroll
        for (int j = 0; j < 2; ++j) {
            int cg = nt * 8 + ec + j;
            float sqc = s_sq[warp][cg];
            float wc  = __shfl_sync(FULLM, wgt, cg);
#pragma unroll
            for (int h = 0; h < 2; ++h) {
                // rows 0-15
                float gA = accA[nt][h * 2 + j];
                float d2 = sqr[h] + sqc - 2.f * gA;
                float dv = (d2 > 0.f) ? sqrt_approx(d2) : 0.f;
                dp[h] += wc * dv;
                // rows 16-31 (lower-left from transposed stash)
                float gB = (nt >= 2) ? accB[nt - 2][h * 2 + j]
                                     : s_st[warp][cg][er + 8 * h];
                float e2 = sqr[2 + h] + sqc - 2.f * gB;
                float ev = (e2 > 0.f) ? sqrt_approx(e2) : 0.f;
                dp[2 + h] += wc * ev;
            }
        }
    }
#pragma unroll
    for (int q = 0; q < 4; ++q) {
        dp[q] += __shfl_xor_sync(FULLM, dp[q], 1);
        dp[q] += __shfl_xor_sync(FULLM, dp[q], 2);
    }
    if ((lane & 3) == 0) {
        s_dagg[warp][er]      = dp[0];
        s_dagg[warp][er + 8]  = dp[1];
        s_dagg[warp][16 + er] = dp[2];
        s_dagg[warp][24 + er] = dp[3];
    }
    __syncwarp();

    // ---- softmax + weight correction (k = lane) ----
    float dg = s_dagg[warp][lane];
    if (msk || !isfinite(dg)) dg = FLT_MAX;
    float neg = -dg;
    float mx  = warp_max32(neg);
    float ev  = __expf(neg - mx);
    float se  = warp_sum32(ev);
    float rr  = ev / se;
    rr *= wgt;
    float sr = warp_sum32(rr);
    rr = rr / sr;
    if (msk) rr = 0.f;
    s_r[warp][lane] = rr;
    __syncwarp();

    // ---- out[node][d] = sum_k r[k] * (hi+lo)[idx_k][d] + bias[d] ----
    float4 b4 = reinterpret_cast<const float4*>(bias)[lane];
    float o0 = 0.f, o1 = 0.f, o2 = 0.f, o3 = 0.f;
#pragma unroll
    for (int k4 = 0; k4 < 8; ++k4) {
        uint4  offs = *reinterpret_cast<const uint4*>(&s_off[warp][k4 * 4]);
        float4 rv   = *reinterpret_cast<const float4*>(&s_r[warp][k4 * 4]);
#pragma unroll
        for (int j = 0; j < 4; ++j) {
            unsigned off = (j == 0) ? offs.x : (j == 1) ? offs.y
                         : (j == 2) ? offs.z : offs.w;
            float    rk  = (j == 0) ? rv.x  : (j == 1) ? rv.y
                         : (j == 2) ? rv.z  : rv.w;
            uint4 p = *reinterpret_cast<const uint4*>(g_p + (size_t)off + lane * 4);
            o0 += rk * unpack_val(p.x);
            o1 += rk * unpack_val(p.y);
            o2 += rk * unpack_val(p.z);
            o3 += rk * unpack_val(p.w);
        }
    }
    reinterpret_cast<float4*>(out)[(size_t)node * 32 + lane] =
        make_float4(o0 + b4.x, o1 + b4.y, o2 + b4.z, o3 + b4.w);
}

// ---------------------------------------------------------------------------
extern "C" void kernel_launch(void* const* d_in, const int* in_sizes, int n_in,
                              void* d_out, int out_size) {
    const float* feat   = (const float*)d_in[0];      // [n, 128]
    const float* weight = (const float*)d_in[1];      // [128, 128]
    const float* bias   = (const float*)d_in[2];      // [128]
    const float* tkw    = (const float*)d_in[3];      // [n, 32]
    const void*  tki    = d_in[4];                    // [n, 32] int32 or int64

    float* out = (float*)d_out;
    const int n = in_sizes[0] / D;

    cudaFuncSetAttribute(proj_mma, cudaFuncAttributeMaxDynamicSharedMemorySize,
                         SMEM_PROJ);

    wconv<<<128, 128>>>(weight);
    proj_mma<<<(n + 63) / 64, 128, SMEM_PROJ>>>(feat, n);
    node_kernel<<<(n + 1) / 2, 64>>>(tki, tkw, bias, out, n);
}

// round 17
// speedup vs baseline: 1.4774x; 1.4774x over previous
#include <cuda_runtime.h>
#include <cuda_bf16.h>
#include <float.h>

#define D 128
#define KN 32
#define MAXN 50000
#define CSTR 40       // node: bf16 elems per chunk row (32 + 8 pad) -> 80 B
#define PSTR 136      // proj: bf16 elems per smem row (128 + 8 pad)
#define FULLM 0xffffffffu

// packed projected features: per element u32 = (lo_bf16 << 16) | hi_bf16
__device__ unsigned g_p[(size_t)MAXN * D];
// transposed weight hi/lo (wt[n][k]), bf16
__device__ __nv_bfloat16 g_wt_hi[D * D];
__device__ __nv_bfloat16 g_wt_lo[D * D];

// ---- mma / ldmatrix helpers ----
__device__ __forceinline__ void ldm_x4(unsigned (&r)[4], unsigned addr) {
    asm volatile("ldmatrix.sync.aligned.m8n8.x4.shared.b16 {%0,%1,%2,%3}, [%4];"
                 : "=r"(r[0]), "=r"(r[1]), "=r"(r[2]), "=r"(r[3]) : "r"(addr));
}
__device__ __forceinline__ void mma4(float* d, const unsigned* a,
                                     unsigned b0, unsigned b1) {
    asm volatile(
        "mma.sync.aligned.m16n8k16.row.col.f32.bf16.bf16.f32 "
        "{%0,%1,%2,%3},{%4,%5,%6,%7},{%8,%9},{%0,%1,%2,%3};"
        : "+f"(d[0]), "+f"(d[1]), "+f"(d[2]), "+f"(d[3])
        : "r"(a[0]), "r"(a[1]), "r"(a[2]), "r"(a[3]), "r"(b0), "r"(b1));
}
__device__ __forceinline__ float sqrt_approx(float x) {
    float r;
    asm("sqrt.approx.f32 %0, %1;" : "=f"(r) : "f"(x));
    return r;
}
// unpack helpers: element fp32 value = hi + lo
__device__ __forceinline__ float unpack_val(unsigned p) {
    return __uint_as_float(p << 16) + __uint_as_float(p & 0xffff0000u);
}
__device__ __forceinline__ unsigned bf2u(__nv_bfloat16 a, __nv_bfloat16 b) {
    __nv_bfloat162 p = __halves2bfloat162(a, b);
    return *reinterpret_cast<unsigned*>(&p);
}
__device__ __forceinline__ unsigned packhl(float v) {
    __nv_bfloat16 h = __float2bfloat16_rn(v);
    __nv_bfloat16 l = __float2bfloat16_rn(v - __bfloat162float(h));
    unsigned hb = *reinterpret_cast<unsigned short*>(&h);
    unsigned lb = *reinterpret_cast<unsigned short*>(&l);
    return (lb << 16) | hb;
}
__device__ __forceinline__ float warp_max32(float v) {
#pragma unroll
    for (int off = 16; off > 0; off >>= 1)
        v = fmaxf(v, __shfl_xor_sync(FULLM, v, off));
    return v;
}
__device__ __forceinline__ float warp_sum32(float v) {
#pragma unroll
    for (int off = 16; off > 0; off >>= 1)
        v += __shfl_xor_sync(FULLM, v, off);
    return v;
}

// ---------------------------------------------------------------------------
// wconv: weight[k][n] fp32 -> transposed bf16 hi/lo wt[n][k]
// ---------------------------------------------------------------------------
__global__ __launch_bounds__(128) void wconv(const float* __restrict__ weight) {
    int idx = blockIdx.x * 128 + threadIdx.x;   // grid 128 x 128
    int k = idx >> 7, nn = idx & 127;
    float v = weight[idx];
    __nv_bfloat16 h = __float2bfloat16_rn(v);
    __nv_bfloat16 l = __float2bfloat16_rn(v - __bfloat162float(h));
    g_wt_hi[nn * D + k] = h;
    g_wt_lo[nn * D + k] = l;
}

// ---------------------------------------------------------------------------
// proj_mma: h = feat @ weight via bf16 hi/lo mma.sync, packed epilogue.
// block = 128 thr (4 warps), tile m64 x n128, k=128. 104 KB dynamic smem.
// ---------------------------------------------------------------------------
#define SM_FA_HI 0
#define SM_FA_LO (64 * PSTR)
#define SM_WB_HI (2 * 64 * PSTR)
#define SM_WB_LO (2 * 64 * PSTR + 128 * PSTR)
#define SMEM_PROJ ((2 * 64 * PSTR + 2 * 128 * PSTR) * 2)

__global__ __launch_bounds__(128) void proj_mma(const float* __restrict__ feat,
                                                int n) {
    extern __shared__ __align__(16) unsigned short sm[];
    unsigned short* fa_hi = sm + SM_FA_HI;
    unsigned short* fa_lo = sm + SM_FA_LO;
    unsigned short* wb_hi = sm + SM_WB_HI;
    unsigned short* wb_lo = sm + SM_WB_LO;

    const int tid  = threadIdx.x;
    const int lane = tid & 31;
    const int warp = tid >> 5;
    const int row0 = blockIdx.x * 64;

    // ---- stage feat tile (64 x 128 fp32 -> hi/lo bf16) ----
#pragma unroll
    for (int i = 0; i < 16; ++i) {
        int lin = i * 128 + tid;
        int r = lin >> 5, c = lin & 31;       // c = float4 index
        int row = row0 + r;
        float4 v = make_float4(0.f, 0.f, 0.f, 0.f);
        if (row < n) v = reinterpret_cast<const float4*>(feat)[(size_t)row * 32 + c];
        __nv_bfloat16 hx = __float2bfloat16_rn(v.x);
        __nv_bfloat16 hy = __float2bfloat16_rn(v.y);
        __nv_bfloat16 hz = __float2bfloat16_rn(v.z);
        __nv_bfloat16 hw = __float2bfloat16_rn(v.w);
        __nv_bfloat16 lx = __float2bfloat16_rn(v.x - __bfloat162float(hx));
        __nv_bfloat16 ly = __float2bfloat16_rn(v.y - __bfloat162float(hy));
        __nv_bfloat16 lz = __float2bfloat16_rn(v.z - __bfloat162float(hz));
        __nv_bfloat16 lw = __float2bfloat16_rn(v.w - __bfloat162float(hw));
        *reinterpret_cast<uint2*>(&fa_hi[r * PSTR + c * 4]) =
            make_uint2(bf2u(hx, hy), bf2u(hz, hw));
        *reinterpret_cast<uint2*>(&fa_lo[r * PSTR + c * 4]) =
            make_uint2(bf2u(lx, ly), bf2u(lz, lw));
    }

    // ---- stage weight tiles (128 x 128 bf16 each) ----
#pragma unroll
    for (int i = 0; i < 16; ++i) {
        int lin = i * 128 + tid;
        int r = lin >> 4, c = lin & 15;       // c = 8-elem (16 B) chunk
        uint4 hv = reinterpret_cast<const uint4*>(g_wt_hi + r * D)[c];
        uint4 lv = reinterpret_cast<const uint4*>(g_wt_lo + r * D)[c];
        *reinterpret_cast<uint4*>(&wb_hi[r * PSTR + c * 8]) = hv;
        *reinterpret_cast<uint4*>(&wb_lo[r * PSTR + c * 8]) = lv;
    }
    __syncthreads();

    // ---- mma mainloop: warp computes rows mw..mw+15, all n=128 ----
    const int mw = warp * 16;
    float acc[16][4];
#pragma unroll
    for (int t = 0; t < 16; ++t)
#pragma unroll
        for (int i = 0; i < 4; ++i) acc[t][i] = 0.f;

    const int trow = (lane & 7) + 8 * ((lane >> 3) & 1);
    const int tcol = 8 * (lane >> 4);
    const unsigned faHiB = (unsigned)__cvta_generic_to_shared(fa_hi);
    const unsigned faLoB = (unsigned)__cvta_generic_to_shared(fa_lo);
    const unsigned wbHiB = (unsigned)__cvta_generic_to_shared(wb_hi);
    const unsigned wbLoB = (unsigned)__cvta_generic_to_shared(wb_lo);

#pragma unroll
    for (int kk = 0; kk < D; kk += 16) {
        unsigned aoff = (unsigned)(((mw + trow) * PSTR + kk + tcol) * 2);
        unsigned ahi[4], alo[4];
        ldm_x4(ahi, faHiB + aoff);
        ldm_x4(alo, faLoB + aoff);

#pragma unroll
        for (int j = 0; j < 8; ++j) {         // n-pair j covers n = 16j..16j+15
            unsigned boff = (unsigned)(((16 * j + trow) * PSTR + kk + tcol) * 2);
            unsigned bh[4], bl[4];
            ldm_x4(bh, wbHiB + boff);
            ldm_x4(bl, wbLoB + boff);
            mma4(acc[2 * j],     ahi, bh[0], bh[2]);
            mma4(acc[2 * j],     ahi, bl[0], bl[2]);
            mma4(acc[2 * j],     alo, bh[0], bh[2]);
            mma4(acc[2 * j + 1], ahi, bh[1], bh[3]);
            mma4(acc[2 * j + 1], ahi, bl[1], bl[3]);
            mma4(acc[2 * j + 1], alo, bh[1], bh[3]);
        }
    }

    // ---- epilogue: pack to g_p ----
    const int er = lane >> 2;
    const int ec = (lane & 3) * 2;
#pragma unroll
    for (int h = 0; h < 2; ++h) {
        int row = row0 + mw + er + 8 * h;
        if (row < n) {
#pragma unroll
            for (int t = 0; t < 16; ++t) {
                unsigned p0 = packhl(acc[t][2 * h]);
                unsigned p1 = packhl(acc[t][2 * h + 1]);
                *reinterpret_cast<uint2*>(g_p + (size_t)row * D + 8 * t + ec) =
                    make_uint2(p0, p1);
            }
        }
    }
}

// ---------------------------------------------------------------------------
// Kernel B: one WARP per node (proven R11 dataflow: packed L2-resident array,
// LDG->PRMT->STS gather, full 8-tile Gram in registers, shfl broadcasts).
// ---------------------------------------------------------------------------
__global__ __launch_bounds__(64, 16) void node_kernel(const void* __restrict__ top_k_idx,
                                                      const float* __restrict__ top_k_w,
                                                      const float* __restrict__ bias,
                                                      float* __restrict__ out,
                                                      int n) {
    __shared__ __align__(16) unsigned short Ahi[2][KN][CSTR];
    __shared__ __align__(16) unsigned short Alo[2][KN][CSTR];
    __shared__ float s_sq[2][KN];
    __shared__ float s_dagg[2][KN];

    const int warp = threadIdx.x >> 5;
    const int lane = threadIdx.x & 31;
    const int node = blockIdx.x * 2 + warp;
    if (node >= n) return;

    int bad = 0;
    if (lane < 16) {
        long long v = reinterpret_cast<const long long*>(top_k_idx)[lane];
        bad = (v < -1 || v >= (long long)n);
    }
    const bool is64 = (__ballot_sync(FULLM, bad) == 0u);

    long long id = is64
        ? reinterpret_cast<const long long*>(top_k_idx)[(size_t)node * KN + lane]
        : (long long)reinterpret_cast<const int*>(top_k_idx)[(size_t)node * KN + lane];
    const int msk = (id < 0);
    int nbr = msk ? 0 : (int)id;
    if (nbr >= n) nbr = 0;
    const float wgt = msk ? 0.f : top_k_w[(size_t)node * KN + lane];

    unsigned short (*ahi)[CSTR] = Ahi[warp];
    unsigned short (*alo)[CSTR] = Alo[warp];

    float acc[2][4][4];
#pragma unroll
    for (int a = 0; a < 2; ++a)
#pragma unroll
        for (int b = 0; b < 4; ++b)
#pragma unroll
            for (int i = 0; i < 4; ++i) acc[a][b][i] = 0.f;

    const int trow = (lane & 7) + 8 * ((lane >> 3) & 1);
    const int tcol = 8 * (lane >> 4);
    const unsigned hiB = (unsigned)__cvta_generic_to_shared(&ahi[0][0]);
    const unsigned loB = (unsigned)__cvta_generic_to_shared(&alo[0][0]);

    const int gq = lane >> 3;
    const int gc = lane & 7;

#pragma unroll
    for (int chunk = 0; chunk < 4; ++chunk) {
        // ---- gather packed chunk rows; split hi/lo via PRMT ----
#pragma unroll
        for (int it = 0; it < 8; ++it) {
            int r = it * 4 + gq;
            int src = __shfl_sync(FULLM, nbr, r);
            uint4 p = *reinterpret_cast<const uint4*>(
                g_p + (size_t)src * D + chunk * 32 + gc * 4);
            unsigned h01 = __byte_perm(p.x, p.y, 0x5410);
            unsigned h23 = __byte_perm(p.z, p.w, 0x5410);
            unsigned l01 = __byte_perm(p.x, p.y, 0x7632);
            unsigned l23 = __byte_perm(p.z, p.w, 0x7632);
            *reinterpret_cast<uint2*>(&ahi[r][gc * 4]) = make_uint2(h01, h23);
            *reinterpret_cast<uint2*>(&alo[r][gc * 4]) = make_uint2(l01, l23);
        }
        __syncwarp();

        // ---- mma-accumulate this chunk (k = 0..31) ----
#pragma unroll
        for (int kk = 0; kk < 32; kk += 16) {
            unsigned o0 = (unsigned)((trow * CSTR + kk + tcol) * 2);
            unsigned o1 = (unsigned)(((16 + trow) * CSTR + kk + tcol) * 2);
            unsigned h0[4], h1[4], l0[4], l1[4];
            ldm_x4(h0, hiB + o0);
            ldm_x4(h1, hiB + o1);
            ldm_x4(l0, loB + o0);
            ldm_x4(l1, loB + o1);

#pragma unroll
            for (int mt = 0; mt < 2; ++mt) {
                const unsigned* Ah = mt ? h1 : h0;
                const unsigned* Al = mt ? l1 : l0;
#pragma unroll
                for (int nt = 0; nt < 4; ++nt) {
                    const unsigned* Bh = (nt < 2) ? h0 : h1;
                    const unsigned* Bl = (nt < 2) ? l0 : l1;
                    unsigned bh0 = (nt & 1) ? Bh[1] : Bh[0];
                    unsigned bh1 = (nt & 1) ? Bh[3] : Bh[2];
                    unsigned bl0 = (nt & 1) ? Bl[1] : Bl[0];
                    unsigned bl1 = (nt & 1) ? Bl[3] : Bl[2];
                    mma4(acc[mt][nt], Ah, bh0, bh1);
                    mma4(acc[mt][nt], Ah, bl0, bl1);
                    mma4(acc[mt][nt], Al, bh0, bh1);
                }
            }
        }
        __syncwarp();
    }

    const int er = lane >> 2;
    const int ec = (lane & 3) * 2;

#pragma unroll
    for (int mt = 0; mt < 2; ++mt)
#pragma unroll
        for (int nt = 0; nt < 4; ++nt)
#pragma unroll
            for (int i = 0; i < 4; ++i) {
                int rg = mt * 16 + er + ((i >> 1) << 3);
                int cg = nt * 8 + ec + (i & 1);
                if (rg == cg) s_sq[warp][rg] = acc[mt][nt][i];
            }
    __syncwarp();

    float dp[4] = {0.f, 0.f, 0.f, 0.f};
    const float sqr[4] = { s_sq[warp][er],      s_sq[warp][er + 8],
                           s_sq[warp][16 + er], s_sq[warp][24 + er] };
#pragma unroll
    for (int nt = 0; nt < 4; ++nt) {
#pragma unroll
        for (int j = 0; j < 2; ++j) {
            int cg = nt * 8 + ec + j;
            float sqc = s_sq[warp][cg];
            float wc  = __shfl_sync(FULLM, wgt, cg);
#pragma unroll
            for (int mt = 0; mt < 2; ++mt) {
#pragma unroll
                for (int h = 0; h < 2; ++h) {
                    float g  = acc[mt][nt][h * 2 + j];
                    float d2 = sqr[mt * 2 + h] + sqc - 2.f * g;
                    float dv = (d2 > 0.f) ? sqrt_approx(d2) : 0.f;
                    dp[mt * 2 + h] += wc * dv;
                }
            }
        }
    }
#pragma unroll
    for (int q = 0; q < 4; ++q) {
        dp[q] += __shfl_xor_sync(FULLM, dp[q], 1);
        dp[q] += __shfl_xor_sync(FULLM, dp[q], 2);
    }
    if ((lane & 3) == 0) {
        s_dagg[warp][er]      = dp[0];
        s_dagg[warp][er + 8]  = dp[1];
        s_dagg[warp][16 + er] = dp[2];
        s_dagg[warp][24 + er] = dp[3];
    }
    __syncwarp();

    float dg = s_dagg[warp][lane];
    if (msk || !isfinite(dg)) dg = FLT_MAX;
    float neg = -dg;
    float mx  = warp_max32(neg);
    float ev  = __expf(neg - mx);
    float se  = warp_sum32(ev);
    float rr  = ev / se;
    rr *= wgt;
    float sr = warp_sum32(rr);
    rr = rr / sr;
    if (msk) rr = 0.f;

    // ---- out[node][d] = sum_k r[k] * (hi+lo)[idx_k][d] + bias[d] ----
    float4 b4 = reinterpret_cast<const float4*>(bias)[lane];
    float o0 = 0.f, o1 = 0.f, o2 = 0.f, o3 = 0.f;
#pragma unroll 8
    for (int k = 0; k < KN; ++k) {
        float rk  = __shfl_sync(FULLM, rr, k);
        int   src = __shfl_sync(FULLM, nbr, k);
        uint4 p = *reinterpret_cast<const uint4*>(g_p + (size_t)src * D + lane * 4);
        o0 += rk * unpack_val(p.x);
        o1 += rk * unpack_val(p.y);
        o2 += rk * unpack_val(p.z);
        o3 += rk * unpack_val(p.w);
    }
    reinterpret_cast<float4*>(out)[(size_t)node * 32 + lane] =
        make_float4(o0 + b4.x, o1 + b4.y, o2 + b4.z, o3 + b4.w);
}

// ---------------------------------------------------------------------------
extern "C" void kernel_launch(void* const* d_in, const int* in_sizes, int n_in,
                              void* d_out, int out_size) {
    const float* feat   = (const float*)d_in[0];      // [n, 128]
    const float* weight = (const float*)d_in[1];      // [128, 128]
    const float* bias   = (const float*)d_in[2];      // [128]
    const float* tkw    = (const float*)d_in[3];      // [n, 32]
    const void*  tki    = d_in[4];                    // [n, 32] int32 or int64

    float* out = (float*)d_out;
    const int n = in_sizes[0] / D;

    cudaFuncSetAttribute(proj_mma, cudaFuncAttributeMaxDynamicSharedMemorySize,
                         SMEM_PROJ);

    wconv<<<128, 128>>>(weight);
    proj_mma<<<(n + 63) / 64, 128, SMEM_PROJ>>>(feat, n);
    node_kernel<<<(n + 1) / 2, 64>>>(tki, tkw, bias, out, n);
}